// round 1
// baseline (speedup 1.0000x reference)
#include <cuda_runtime.h>

#define NB 256
#define NS 512
#define ND 256
#define NA 128
#define TS 128
#define TK 32

// scratch for exp-scores (allocation-free rule: device global)
__device__ float g_scores[NB * NS];

__device__ __forceinline__ unsigned long long pack2(float lo, float hi) {
    unsigned long long r;
    asm("mov.b64 %0, {%1, %2};" : "=l"(r) : "f"(lo), "f"(hi));
    return r;
}
__device__ __forceinline__ void unpack2(unsigned long long v, float& lo, float& hi) {
    asm("mov.b64 {%0, %1}, %2;" : "=f"(lo), "=f"(hi) : "l"(v));
}
// packed dual-FMA: acc.{lo,hi} += a.{lo,hi} * b.{lo,hi}   (SASS FFMA2)
__device__ __forceinline__ void ffma2(unsigned long long& acc, unsigned long long a, unsigned long long b) {
    asm("fma.rn.f32x2 %0, %1, %2, %0;" : "+l"(acc) : "l"(a), "l"(b));
}
// tanh(x) = 1 - 2/(e^{2x}+1); robust at +-inf, abs err ~1e-7
__device__ __forceinline__ float fast_tanh(float x) {
    float e = __expf(2.0f * x);
    return 1.0f - __fdividef(2.0f, e + 1.0f);
}

// ---------------------------------------------------------------------------
// Kernel 1: exp-scores.  One CTA computes a 128(s) x 128(att) uit tile for one
// batch, fused tanh + dot(u) + exp.  FFMA2 micro-tile 8x8 per thread.
// ---------------------------------------------------------------------------
__global__ void __launch_bounds__(256, 2) scores_kernel(
    const float* __restrict__ x, const float* __restrict__ W,
    const float* __restrict__ bias, const float* __restrict__ u)
{
    __shared__ float xs[TS * 33];     // 128 rows x TK, padded to 33 (bank-conflict-free broadcast)
    __shared__ float ws[TK * NA];     // TK x 128
    __shared__ float bsm[NA];
    __shared__ float usm[NA];
    float* red = xs;                  // reuse xs for the logit reduction (2176 <= 4224 floats)

    const int b   = blockIdx.y;
    const int s0  = blockIdx.x * TS;
    const int tid = threadIdx.x;
    const int tx  = tid & 15;         // column group
    const int ty  = tid >> 4;         // row group

    if (tid < NA) { bsm[tid] = bias[tid]; usm[tid] = u[tid]; }

    unsigned long long acc[8][4];     // [row i][col-pair p]; pair covers cols {2tx+32p, +1}
#pragma unroll
    for (int i = 0; i < 8; i++)
#pragma unroll
        for (int p = 0; p < 4; p++) acc[i][p] = 0ull;

    const float* xb = x + ((size_t)b * NS + s0) * ND;

    for (int k0 = 0; k0 < ND; k0 += TK) {
        __syncthreads();
        // load x tile (TS x TK) -> padded smem (scalar stores keep 16B-align irrelevant)
#pragma unroll
        for (int it = 0; it < 4; it++) {
            int t = tid + it * 256;
            int r = t >> 3;
            int c = (t & 7) << 2;
            float4 v = *(const float4*)(xb + (size_t)r * ND + k0 + c);
            xs[r * 33 + c + 0] = v.x;
            xs[r * 33 + c + 1] = v.y;
            xs[r * 33 + c + 2] = v.z;
            xs[r * 33 + c + 3] = v.w;
        }
        // load W tile (TK x NA)
#pragma unroll
        for (int it = 0; it < 4; it++) {
            int t = tid + it * 256;
            int r = t >> 5;
            int c = (t & 31) << 2;
            *(float4*)(ws + r * NA + c) = *(const float4*)(W + (size_t)(k0 + r) * NA + c);
        }
        __syncthreads();
#pragma unroll
        for (int kk = 0; kk < TK; kk++) {
            unsigned long long bp[4];
#pragma unroll
            for (int p = 0; p < 4; p++)   // coalesced LDS.64: lane addrs 8B-consecutive
                bp[p] = *(const unsigned long long*)(ws + kk * NA + 2 * tx + 32 * p);
#pragma unroll
            for (int i = 0; i < 8; i++) {
                float a = xs[(ty * 8 + i) * 33 + kk];   // broadcast, padded rows -> 1 phase
                unsigned long long ap = pack2(a, a);
#pragma unroll
                for (int p = 0; p < 4; p++) ffma2(acc[i][p], ap, bp[p]);
            }
        }
    }
    __syncthreads();   // all xs reads done; safe to reuse as `red`

    // epilogue: bias + tanh + dot(u) partial per thread
#pragma unroll
    for (int i = 0; i < 8; i++) {
        float partial = 0.0f;
#pragma unroll
        for (int p = 0; p < 4; p++) {
            float lo, hi; unpack2(acc[i][p], lo, hi);
            int c0 = 2 * tx + 32 * p;
            partial += fast_tanh(lo + bsm[c0])     * usm[c0];
            partial += fast_tanh(hi + bsm[c0 + 1]) * usm[c0 + 1];
        }
        red[(ty * 8 + i) * 17 + tx] = partial;   // stride 17: conflict-free
    }
    __syncthreads();
    if (tid < TS) {
        float lg = 0.0f;
#pragma unroll
        for (int j = 0; j < 16; j++) lg += red[tid * 17 + j];
        g_scores[b * NS + s0 + tid] = expf(lg);  // faithful: no max-subtraction (matches ref)
    }
}

// ---------------------------------------------------------------------------
// Kernel 2: per-batch normalize + weighted sum over S.  HBM-bound GEMV.
// ---------------------------------------------------------------------------
__global__ void __launch_bounds__(256) out_kernel(const float* __restrict__ x, float* __restrict__ out)
{
    __shared__ float ssm[NS];
    __shared__ float rbuf[256];
    const int b = blockIdx.x;
    const int tid = threadIdx.x;

    float v0 = g_scores[b * NS + tid];
    float v1 = g_scores[b * NS + 256 + tid];
    ssm[tid] = v0;
    ssm[tid + 256] = v1;
    rbuf[tid] = v0 + v1;
    __syncthreads();
#pragma unroll
    for (int st = 128; st > 0; st >>= 1) {
        if (tid < st) rbuf[tid] += rbuf[tid + st];
        __syncthreads();
    }
    const float inv = 1.0f / (rbuf[0] + 1e-8f);

    const float* xb = x + (size_t)b * NS * ND;
    float a0 = 0.f, a1 = 0.f, a2 = 0.f, a3 = 0.f;
#pragma unroll 4
    for (int s = 0; s < NS; s += 4) {
        a0 += ssm[s + 0] * xb[(size_t)(s + 0) * ND + tid];
        a1 += ssm[s + 1] * xb[(size_t)(s + 1) * ND + tid];
        a2 += ssm[s + 2] * xb[(size_t)(s + 2) * ND + tid];
        a3 += ssm[s + 3] * xb[(size_t)(s + 3) * ND + tid];
    }
    out[b * ND + tid] = (a0 + a1 + a2 + a3) * inv;
}

extern "C" void kernel_launch(void* const* d_in, const int* in_sizes, int n_in,
                              void* d_out, int out_size) {
    const float* x    = (const float*)d_in[0];
    const float* W    = (const float*)d_in[1];
    const float* bias = (const float*)d_in[2];
    const float* u    = (const float*)d_in[3];
    float* out        = (float*)d_out;

    scores_kernel<<<dim3(NS / TS, NB), 256>>>(x, W, bias, u);
    out_kernel<<<NB, 256>>>(x, out);
}

// round 2
// speedup vs baseline: 1.1308x; 1.1308x over previous
#include <cuda_runtime.h>

#define NB 256
#define NS 512
#define ND 256
#define NA 128
#define TS 128
#define TK 32
#define XSTR 36           // x-tile row stride (16B-aligned for cp.async, even for float2 reads)
#define NTILE (NS / TS)   // 4

// scratch (allocation-free rule: device globals)
__device__ float g_part[NB * NTILE * ND];
__device__ float g_esum[NB * NTILE];

// dynamic smem layout (floats):
//   xs[2][TS*XSTR]  = 2*4608
//   ws[2][TK*NA]    = 2*4096
//   bsm[NA], usm[NA], es[TS]
#define SMEM_FLOATS (2 * TS * XSTR + 2 * TK * NA + 2 * NA + TS)

__device__ __forceinline__ unsigned long long pack2(float lo, float hi) {
    unsigned long long r;
    asm("mov.b64 %0, {%1, %2};" : "=l"(r) : "f"(lo), "f"(hi));
    return r;
}
__device__ __forceinline__ void unpack2(unsigned long long v, float& lo, float& hi) {
    asm("mov.b64 {%0, %1}, %2;" : "=f"(lo), "=f"(hi) : "l"(v));
}
__device__ __forceinline__ void ffma2(unsigned long long& acc, unsigned long long a, unsigned long long b) {
    asm("fma.rn.f32x2 %0, %1, %2, %0;" : "+l"(acc) : "l"(a), "l"(b));
}
__device__ __forceinline__ float fast_tanh(float x) {
    float e = __expf(2.0f * x);
    return 1.0f - __fdividef(2.0f, e + 1.0f);
}
__device__ __forceinline__ void cp16(float* dst, const float* src) {
    unsigned saddr = (unsigned)__cvta_generic_to_shared(dst);
    asm volatile("cp.async.cg.shared.global [%0], [%1], 16;\n" :: "r"(saddr), "l"(src));
}
__device__ __forceinline__ void cp_commit() { asm volatile("cp.async.commit_group;\n"); }
template<int N> __device__ __forceinline__ void cp_wait() {
    asm volatile("cp.async.wait_group %0;\n" :: "n"(N));
}

// ---------------------------------------------------------------------------
// Kernel 1: fused scores + per-tile weighted partial sum.
// CTA = (s-tile, batch). 128(s) x 128(att) FFMA2 GEMM, tanh, dot(u), exp,
// then p[d] = sum_s e_s * x[s,d] for its 128 rows.
// ---------------------------------------------------------------------------
__global__ void __launch_bounds__(256, 2) scores_kernel(
    const float* __restrict__ x, const float* __restrict__ W,
    const float* __restrict__ bias, const float* __restrict__ u)
{
    extern __shared__ float smem[];
    float* xs[2] = { smem, smem + TS * XSTR };
    float* ws[2] = { smem + 2 * TS * XSTR, smem + 2 * TS * XSTR + TK * NA };
    float* bsm = smem + 2 * TS * XSTR + 2 * TK * NA;
    float* usm = bsm + NA;
    float* es  = usm + NA;
    float* red = xs[0];   // reuse after mainloop (needs 128*17 <= 4608)

    const int b    = blockIdx.y;
    const int tile = blockIdx.x;
    const int s0   = tile * TS;
    const int tid  = threadIdx.x;
    const int tx   = tid & 15;
    const int ty   = tid >> 4;

    const float* xb = x + ((size_t)b * NS + s0) * ND;

    if (tid < NA) { bsm[tid] = bias[tid]; usm[tid] = u[tid]; }

    // cp.async tile issue: one group = x tile (TS x TK) + W tile (TK x NA)
    auto issue = [&](int bufi, int k0) {
#pragma unroll
        for (int it = 0; it < 4; it++) {
            int t = tid + it * 256;
            int r = t >> 3;
            int c = (t & 7) << 2;
            cp16(&xs[bufi][r * XSTR + c], xb + (size_t)r * ND + k0 + c);
        }
#pragma unroll
        for (int it = 0; it < 4; it++) {
            int t = tid + it * 256;
            int r = t >> 5;
            int c = (t & 31) << 2;
            cp16(&ws[bufi][r * NA + c], W + (size_t)(k0 + r) * NA + c);
        }
        cp_commit();
    };

    unsigned long long acc[8][4];
#pragma unroll
    for (int i = 0; i < 8; i++)
#pragma unroll
        for (int p = 0; p < 4; p++) acc[i][p] = 0ull;

    issue(0, 0);   // prologue

#pragma unroll 1
    for (int i = 0; i < ND / TK; i++) {
        if (i < ND / TK - 1) issue((i + 1) & 1, (i + 1) * TK);
        if (i < ND / TK - 1) cp_wait<1>(); else cp_wait<0>();
        __syncthreads();

        const float* xc = xs[i & 1];
        const float* wc = ws[i & 1];
#pragma unroll
        for (int kk = 0; kk < TK; kk += 2) {
            float2 ax[8];
#pragma unroll
            for (int r = 0; r < 8; r++)
                ax[r] = *(const float2*)(xc + (ty * 8 + r) * XSTR + kk);
#pragma unroll
            for (int sub = 0; sub < 2; sub++) {
                unsigned long long bp[4];
#pragma unroll
                for (int p = 0; p < 4; p++)
                    bp[p] = *(const unsigned long long*)(wc + (kk + sub) * NA + 2 * tx + 32 * p);
#pragma unroll
                for (int r = 0; r < 8; r++) {
                    float a = sub ? ax[r].y : ax[r].x;
                    unsigned long long ap = pack2(a, a);
#pragma unroll
                    for (int p = 0; p < 4; p++) ffma2(acc[r][p], ap, bp[p]);
                }
            }
        }
        __syncthreads();
    }

    // epilogue: bias + tanh + dot(u) partials
#pragma unroll
    for (int r = 0; r < 8; r++) {
        float partial = 0.0f;
#pragma unroll
        for (int p = 0; p < 4; p++) {
            float lo, hi; unpack2(acc[r][p], lo, hi);
            int c0 = 2 * tx + 32 * p;
            partial += fast_tanh(lo + bsm[c0])     * usm[c0];
            partial += fast_tanh(hi + bsm[c0 + 1]) * usm[c0 + 1];
        }
        red[(ty * 8 + r) * 17 + tx] = partial;
    }
    __syncthreads();

    if (tid < TS) {
        float lg = 0.0f;
#pragma unroll
        for (int j = 0; j < 16; j++) lg += red[tid * 17 + j];
        es[tid] = expf(lg);   // faithful: no max-subtraction (matches reference)
    }
    __syncthreads();

    // exp-sum for this tile (deterministic tree over es)
    if (tid < 64)  red[tid] = es[tid] + es[tid + 64];
    __syncthreads();
    if (tid < 32) {
        float v = red[tid] + red[tid + 32];
#pragma unroll
        for (int off = 16; off > 0; off >>= 1)
            v += __shfl_down_sync(0xffffffffu, v, off);
        if (tid == 0) g_esum[b * NTILE + tile] = v;
    }

    // weighted partial sum over this tile's 128 rows (x re-read: L2-hot)
    float a0 = 0.f, a1 = 0.f, a2 = 0.f, a3 = 0.f;
#pragma unroll 4
    for (int s = 0; s < TS; s += 4) {
        a0 += es[s + 0] * xb[(size_t)(s + 0) * ND + tid];
        a1 += es[s + 1] * xb[(size_t)(s + 1) * ND + tid];
        a2 += es[s + 2] * xb[(size_t)(s + 2) * ND + tid];
        a3 += es[s + 3] * xb[(size_t)(s + 3) * ND + tid];
    }
    g_part[((size_t)b * NTILE + tile) * ND + tid] = (a0 + a1) + (a2 + a3);
}

// ---------------------------------------------------------------------------
// Kernel 2: combine 4 tile partials per batch. ~1MB traffic.
// ---------------------------------------------------------------------------
__global__ void __launch_bounds__(256) finish_kernel(float* __restrict__ out)
{
    const int b = blockIdx.x;
    const int tid = threadIdx.x;
    float s = 0.f;
#pragma unroll
    for (int t = 0; t < NTILE; t++) s += g_esum[b * NTILE + t];
    const float inv = 1.0f / (s + 1e-8f);
    float v = 0.f;
#pragma unroll
    for (int t = 0; t < NTILE; t++) v += g_part[((size_t)b * NTILE + t) * ND + tid];
    out[b * ND + tid] = v * inv;
}

extern "C" void kernel_launch(void* const* d_in, const int* in_sizes, int n_in,
                              void* d_out, int out_size) {
    const float* x    = (const float*)d_in[0];
    const float* W    = (const float*)d_in[1];
    const float* bias = (const float*)d_in[2];
    const float* u    = (const float*)d_in[3];
    float* out        = (float*)d_out;

    const int smem_bytes = SMEM_FLOATS * sizeof(float);
    cudaFuncSetAttribute(scores_kernel, cudaFuncAttributeMaxDynamicSharedMemorySize, smem_bytes);

    scores_kernel<<<dim3(NTILE, NB), 256, smem_bytes>>>(x, W, bias, u);
    finish_kernel<<<NB, 256>>>(out);
}

// round 4
// speedup vs baseline: 2.0323x; 1.7972x over previous
#include <cuda_runtime.h>
#include <cuda_bf16.h>
#include <cstdint>

#define NB 256
#define NS 512
#define ND 256
#define NA 128
#define TS 128
#define NTILE (NS / TS)     // 4
#define KC 32               // K-chunk
#define NCHUNK (ND / KC)    // 8
#define ASTR 40             // padded row stride in bf16 elems (80B: conflict-free ldmatrix)

// ---- scratch (allocation-free rule: device globals) ----
__device__ float g_part[NB * NTILE * ND];
__device__ float g_esum[NB * NTILE];
__device__ __nv_bfloat16 g_wt_hi[NA * ND];   // [n][k] K-major (B col-major for mma)
__device__ __nv_bfloat16 g_wt_lo[NA * ND];

// ---- dynamic smem layout (bytes) ----
#define OFF_ES    0                       // 128 floats
#define OFF_BSM   512
#define OFF_USM   1024
#define OFF_RED   1536                    // 128 floats (logit accum)
#define OFF_TILES 2048
#define HTILE_B   (TS * ASTR * 2)         // 10240 bytes per half-tile
#define OFF_AH(buf) (OFF_TILES + (buf) * 4 * HTILE_B + 0 * HTILE_B)
#define OFF_AL(buf) (OFF_TILES + (buf) * 4 * HTILE_B + 1 * HTILE_B)
#define OFF_BH(buf) (OFF_TILES + (buf) * 4 * HTILE_B + 2 * HTILE_B)
#define OFF_BL(buf) (OFF_TILES + (buf) * 4 * HTILE_B + 3 * HTILE_B)
#define SMEM_TOTAL  (OFF_TILES + 8 * HTILE_B)    // 83968

#define LDSM4(r, addr) \
    asm volatile("ldmatrix.sync.aligned.m8n8.x4.shared.b16 {%0,%1,%2,%3}, [%4];" \
        : "=r"((r)[0]), "=r"((r)[1]), "=r"((r)[2]), "=r"((r)[3]) : "r"(addr))

#define MMA16816(d, a, b0, b1) \
    asm volatile("mma.sync.aligned.m16n8k16.row.col.f32.bf16.bf16.f32 " \
        "{%0,%1,%2,%3},{%4,%5,%6,%7},{%8,%9},{%0,%1,%2,%3};" \
        : "+f"((d)[0]), "+f"((d)[1]), "+f"((d)[2]), "+f"((d)[3]) \
        : "r"((a)[0]), "r"((a)[1]), "r"((a)[2]), "r"((a)[3]), "r"(b0), "r"(b1))

__device__ __forceinline__ void cp16(char* dst, const char* src) {
    unsigned saddr = (unsigned)__cvta_generic_to_shared(dst);
    asm volatile("cp.async.cg.shared.global [%0], [%1], 16;\n" :: "r"(saddr), "l"(src));
}
__device__ __forceinline__ void cp_commit() { asm volatile("cp.async.commit_group;\n"); }
template<int N> __device__ __forceinline__ void cp_wait() {
    asm volatile("cp.async.wait_group %0;\n" :: "n"(N));
}
__device__ __forceinline__ uint32_t pack_bf2(float a, float b) {
    __nv_bfloat162 t = __halves2bfloat162(__float2bfloat16(a), __float2bfloat16(b));
    return *(uint32_t*)&t;
}
__device__ __forceinline__ float fast_tanh(float x) {
    float e = __expf(2.0f * x);
    return 1.0f - __fdividef(2.0f, e + 1.0f);
}

// ---------------------------------------------------------------------------
// Prep: transpose + bf16-split W -> g_wt_hi/lo [n][k].
// ---------------------------------------------------------------------------
__global__ void __launch_bounds__(256) wprep_kernel(const float* __restrict__ W) {
    int idx = blockIdx.x * 256 + threadIdx.x;
    if (idx < ND * NA) {
        int k = idx >> 7;          // d index
        int n = idx & (NA - 1);    // att index
        float w = W[idx];
        __nv_bfloat16 h = __float2bfloat16(w);
        float lo = w - __bfloat162float(h);
        g_wt_hi[n * ND + k] = h;
        g_wt_lo[n * ND + k] = __float2bfloat16(lo);
    }
}

// ---------------------------------------------------------------------------
// Main: bf16-split HMMA GEMM (3 passes) + fused tanh/dot(u)/exp + weighted
// partial sum.  CTA = (s-tile, batch), 8 warps, warp tile 32(M) x 64(N).
// ---------------------------------------------------------------------------
__global__ void __launch_bounds__(256, 2) scores_kernel(
    const float* __restrict__ x, const float* __restrict__ bias,
    const float* __restrict__ u)
{
    extern __shared__ char smem[];
    const uint32_t smb = (uint32_t)__cvta_generic_to_shared(smem);

    const int b    = blockIdx.y;
    const int tile = blockIdx.x;
    const int s0   = tile * TS;
    const int tid  = threadIdx.x;
    const int w    = tid >> 5;
    const int l    = tid & 31;
    const int wm   = w >> 1;       // 0..3  (M groups of 32)
    const int wn   = w & 1;        // 0..1  (N groups of 64)

    float* es  = (float*)(smem + OFF_ES);
    float* bsm = (float*)(smem + OFF_BSM);
    float* usm = (float*)(smem + OFF_USM);
    float* red = (float*)(smem + OFF_RED);

    if (tid < NA) { bsm[tid] = bias[tid]; usm[tid] = u[tid]; }
    if (tid < TS) red[tid] = 0.0f;

    const float* xb = x + ((size_t)b * NS + s0) * ND;

    // ---- x load (registers) / convert+STS helpers ----
    const int xrow  = tid >> 1;
    const int xcolh = tid & 1;
    float4 st[4];
    auto load_x = [&](int c) {
        const float* p = xb + (size_t)xrow * ND + c * KC + xcolh * 16;
#pragma unroll
        for (int i = 0; i < 4; i++) st[i] = ((const float4*)p)[i];
    };
    auto sts_x = [&](int buf) {
        uint32_t hv[8], lv[8];
#pragma unroll
        for (int i = 0; i < 4; i++) {
            float vs[4] = { st[i].x, st[i].y, st[i].z, st[i].w };
            float hs[4], ls[4];
#pragma unroll
            for (int j = 0; j < 4; j++) {
                __nv_bfloat16 h = __float2bfloat16(vs[j]);
                hs[j] = __bfloat162float(h);
                ls[j] = vs[j] - hs[j];
            }
            hv[2*i]   = pack_bf2(vs[0+0]==vs[0+0]?vs[0]:vs[0], vs[1]);  // placeholder avoided below
            hv[2*i]   = pack_bf2(vs[0], vs[1]);
            hv[2*i+1] = pack_bf2(vs[2], vs[3]);
            lv[2*i]   = pack_bf2(ls[0], ls[1]);
            lv[2*i+1] = pack_bf2(ls[2], ls[3]);
        }
        int off = xrow * (ASTR * 2) + xcolh * 32;
        *(uint4*)(smem + OFF_AH(buf) + off)      = make_uint4(hv[0], hv[1], hv[2], hv[3]);
        *(uint4*)(smem + OFF_AH(buf) + off + 16) = make_uint4(hv[4], hv[5], hv[6], hv[7]);
        *(uint4*)(smem + OFF_AL(buf) + off)      = make_uint4(lv[0], lv[1], lv[2], lv[3]);
        *(uint4*)(smem + OFF_AL(buf) + off + 16) = make_uint4(lv[4], lv[5], lv[6], lv[7]);
    };
    auto cp_w = [&](int c, int buf) {
#pragma unroll
        for (int it = 0; it < 4; it++) {
            int idx = tid + it * 256;          // 0..1023
            int h   = idx >> 9;
            int rem = idx & 511;
            int n   = rem >> 2;
            int s   = rem & 3;
            const char* src = (const char*)(h ? g_wt_lo : g_wt_hi) + (size_t)n * (ND * 2) + c * (KC * 2) + s * 16;
            char* dst = smem + (h ? OFF_BL(buf) : OFF_BH(buf)) + n * (ASTR * 2) + s * 16;
            cp16(dst, src);
        }
        cp_commit();
    };

    float acc[2][8][4];
#pragma unroll
    for (int m = 0; m < 2; m++)
#pragma unroll
        for (int nf = 0; nf < 8; nf++)
#pragma unroll
            for (int e = 0; e < 4; e++) acc[m][nf][e] = 0.0f;

    // lane offset for ldmatrix addressing (row = l&15, k-half = l>>4)
    const uint32_t lane_off = (uint32_t)((l & 15) * (ASTR * 2) + (l >> 4) * 16);

    // ---- prologue ----
    load_x(0);
    cp_w(0, 0);
    sts_x(0);

#pragma unroll 1
    for (int c = 0; c < NCHUNK; c++) {
        const int buf = c & 1;
        if (c < NCHUNK - 1) { cp_w(c + 1, buf ^ 1); load_x(c + 1); }
        if (c < NCHUNK - 1) cp_wait<1>(); else cp_wait<0>();
        __syncthreads();

        const uint32_t ah_base = smb + OFF_AH(buf) + (uint32_t)(wm * 32) * (ASTR * 2) + lane_off;
        const uint32_t al_base = smb + OFF_AL(buf) + (uint32_t)(wm * 32) * (ASTR * 2) + lane_off;
        const uint32_t bh_base = smb + OFF_BH(buf) + (uint32_t)(wn * 64) * (ASTR * 2) + lane_off;
        const uint32_t bl_base = smb + OFF_BL(buf) + (uint32_t)(wn * 64) * (ASTR * 2) + lane_off;

#pragma unroll
        for (int kk = 0; kk < KC; kk += 16) {
            uint32_t ah[2][4], al[2][4];
#pragma unroll
            for (int m = 0; m < 2; m++) {
                LDSM4(ah[m], ah_base + m * 16 * (ASTR * 2) + kk * 2);
                LDSM4(al[m], al_base + m * 16 * (ASTR * 2) + kk * 2);
            }
#pragma unroll
            for (int np = 0; np < 4; np++) {
                uint32_t bh[4], bl[4];
                LDSM4(bh, bh_base + np * 16 * (ASTR * 2) + kk * 2);
                LDSM4(bl, bl_base + np * 16 * (ASTR * 2) + kk * 2);
#pragma unroll
                for (int m = 0; m < 2; m++) {
#pragma unroll
                    for (int sn = 0; sn < 2; sn++) {
                        float* d = acc[m][np * 2 + sn];
                        uint32_t h0 = sn ? bh[1] : bh[0], h1 = sn ? bh[3] : bh[2];
                        uint32_t l0 = sn ? bl[1] : bl[0], l1 = sn ? bl[3] : bl[2];
                        MMA16816(d, ah[m], h0, h1);   // hi*hi
                        MMA16816(d, ah[m], l0, l1);   // hi*lo
                        MMA16816(d, al[m], h0, h1);   // lo*hi
                    }
                }
            }
        }
        if (c < NCHUNK - 1) sts_x(buf ^ 1);
        __syncthreads();
    }

    // ---- epilogue: tanh + dot(u) partials -> red[row] (2 contributors/row) ----
    const int g   = l >> 2;    // group id (row within 8)
    const int tig = l & 3;
#pragma unroll
    for (int m = 0; m < 2; m++) {
        float pA = 0.0f, pB = 0.0f;
#pragma unroll
        for (int nf = 0; nf < 8; nf++) {
#pragma unroll
            for (int e = 0; e < 2; e++) {
                int col = wn * 64 + nf * 8 + 2 * tig + e;
                pA += fast_tanh(acc[m][nf][e]     + bsm[col]) * usm[col];
                pB += fast_tanh(acc[m][nf][2 + e] + bsm[col]) * usm[col];
            }
        }
        pA += __shfl_xor_sync(0xffffffffu, pA, 1);
        pA += __shfl_xor_sync(0xffffffffu, pA, 2);
        pB += __shfl_xor_sync(0xffffffffu, pB, 1);
        pB += __shfl_xor_sync(0xffffffffu, pB, 2);
        if (tig == 0) {
            int row = wm * 32 + m * 16 + g;
            atomicAdd(&red[row], pA);       // exactly 2 adds/row: order-independent
            atomicAdd(&red[row + 8], pB);
        }
    }
    __syncthreads();
    if (tid < TS) es[tid] = expf(red[tid]);   // faithful: no max-subtraction
    __syncthreads();

    // tile exp-sum (deterministic tree; red reusable now)
    if (tid < 64) red[tid] = es[tid] + es[tid + 64];
    __syncthreads();
    if (tid < 32) {
        float v = red[tid] + red[tid + 32];
#pragma unroll
        for (int off = 16; off > 0; off >>= 1)
            v += __shfl_down_sync(0xffffffffu, v, off);
        if (tid == 0) g_esum[b * NTILE + tile] = v;
    }

    // weighted partial sum over this tile's rows (x re-read: L2-hot)
    float a0 = 0.f, a1 = 0.f, a2 = 0.f, a3 = 0.f;
#pragma unroll 4
    for (int s = 0; s < TS; s += 4) {
        a0 += es[s + 0] * xb[(size_t)(s + 0) * ND + tid];
        a1 += es[s + 1] * xb[(size_t)(s + 1) * ND + tid];
        a2 += es[s + 2] * xb[(size_t)(s + 2) * ND + tid];
        a3 += es[s + 3] * xb[(size_t)(s + 3) * ND + tid];
    }
    g_part[((size_t)b * NTILE + tile) * ND + tid] = (a0 + a1) + (a2 + a3);
}

// ---------------------------------------------------------------------------
// Combine tile partials.
// ---------------------------------------------------------------------------
__global__ void __launch_bounds__(256) finish_kernel(float* __restrict__ out)
{
    const int b = blockIdx.x;
    const int tid = threadIdx.x;
    float s = 0.f;
#pragma unroll
    for (int t = 0; t < NTILE; t++) s += g_esum[b * NTILE + t];
    const float inv = 1.0f / (s + 1e-8f);
    float v = 0.f;
#pragma unroll
    for (int t = 0; t < NTILE; t++) v += g_part[((size_t)b * NTILE + t) * ND + tid];
    out[b * ND + tid] = v * inv;
}

extern "C" void kernel_launch(void* const* d_in, const int* in_sizes, int n_in,
                              void* d_out, int out_size) {
    const float* x    = (const float*)d_in[0];
    const float* W    = (const float*)d_in[1];
    const float* bias = (const float*)d_in[2];
    const float* u    = (const float*)d_in[3];
    float* out        = (float*)d_out;

    cudaFuncSetAttribute(scores_kernel, cudaFuncAttributeMaxDynamicSharedMemorySize, SMEM_TOTAL);

    wprep_kernel<<<(ND * NA + 255) / 256, 256>>>(W);
    scores_kernel<<<dim3(NTILE, NB), 256, SMEM_TOTAL>>>(x, bias, u);
    finish_kernel<<<NB, 256>>>(out);
}